// round 4
// baseline (speedup 1.0000x reference)
#include <cuda_runtime.h>
#include <cstdint>

#define B_    64
#define S_    1024
#define CIN   5
#define KS    4
#define H1    64
#define H2    16
#define OUTC  32
#define L1    1021
#define C1    22
#define SIGC1 506
#define SC1P  512
#define L2    1018
#define SIGC2 272
#define NC1   16
#define CH1   64

// conv2 tiling
#define TM    128
#define KC    32
#define SAS   130           // As row stride (floats)
#define SZ    66
#define SW    68
#define GEMMF (KC*SAS + KC*128)          // 4160 + 4096 = 8256 floats
#define EPIF  (128*SZ + 64*SW)           // 8448 + 4352 = 12800 floats
#define DSMF  (GEMMF > EPIF ? GEMMF : EPIF)
#define DSMB  (DSMF * 4)

// ---- scratch ----
__device__ float g_h[B_ * L1 * C1];
__device__ float g_s1[(size_t)B_ * L1 * SC1P];
__device__ float g_wdup[KS * SC1P * 128];   // duplicated pairs, 1 MB
__device__ float g_csum[B_ * NC1 * SC1P];
__device__ float g_h2[B_ * L2 * H2];

__device__ __forceinline__ unsigned long long ffma2(
    unsigned long long a, unsigned long long b, unsigned long long c) {
    unsigned long long d;
    asm("fma.rn.f32x2 %0, %1, %2, %3;" : "=l"(d) : "l"(a), "l"(b), "l"(c));
    return d;
}
__device__ __forceinline__ void unpack2(unsigned long long p, float& lo, float& hi) {
    unsigned int a, b;
    asm("mov.b64 {%0, %1}, %2;" : "=r"(a), "=r"(b) : "l"(p));
    lo = __uint_as_float(a); hi = __uint_as_float(b);
}

// ============================================================
// Repack a2_w0 (O,C,K) -> wdup[k][c_pad][2o]=[2o+1]=w
// ============================================================
__global__ void k_repack(const float* __restrict__ w0) {
    int idx = blockIdx.x * blockDim.x + threadIdx.x;   // 0..262143
    int o  = (idx >> 1) & 63;
    int c  = (idx >> 7) & (SC1P - 1);
    int kk = idx >> 16;
    float v = 0.f;
    if (c < SIGC1) v = w0[(o * SIGC1 + c) * KS + kk];
    g_wdup[idx] = v;
}

// ============================================================
// Augment 1
// ============================================================
__global__ __launch_bounds__(128) void k_aug1(
    const float* __restrict__ x,
    const float* __restrict__ w0, const float* __restrict__ b0,
    const float* __restrict__ w1, const float* __restrict__ b1,
    const float* __restrict__ w2, const float* __restrict__ b2)
{
    __shared__ float w0s[H1*CIN*KS], w1s[H1*H1], w2s[H2*H1];
    __shared__ float b0s[H1], b1s[H1], b2s[H2];
    int tid = threadIdx.x;
    for (int i = tid; i < H1*CIN*KS; i += 128) w0s[i] = w0[i];
    for (int i = tid; i < H1*H1;     i += 128) w1s[i] = w1[i];
    for (int i = tid; i < H2*H1;     i += 128) w2s[i] = w2[i];
    if (tid < H1) { b0s[tid] = b0[tid]; b1s[tid] = b1[tid]; }
    if (tid < H2) b2s[tid] = b2[tid];
    __syncthreads();

    int b = blockIdx.y;
    int t = blockIdx.x * 128 + tid;
    if (t >= L1) return;

    float xr[KS][CIN];
#pragma unroll
    for (int k = 0; k < KS; k++)
#pragma unroll
        for (int c = 0; c < CIN; c++)
            xr[k][c] = x[((size_t)(b * S_) + t + k) * CIN + c];

    float z1[H1];
#pragma unroll
    for (int o = 0; o < H1; o++) {
        float s = b0s[o];
#pragma unroll
        for (int c = 0; c < CIN; c++)
#pragma unroll
            for (int k = 0; k < KS; k++)
                s += w0s[(o*CIN + c)*KS + k] * xr[k][c];
        z1[o] = fmaxf(s, 0.f);
    }
    float z3[H2];
#pragma unroll
    for (int o = 0; o < H2; o++) z3[o] = b2s[o];
    for (int o2 = 0; o2 < H1; o2++) {
        float s = b1s[o2];
#pragma unroll
        for (int c = 0; c < H1; c++) s += w1s[o2*H1 + c] * z1[c];
        s = fmaxf(s, 0.f);
#pragma unroll
        for (int o = 0; o < H2; o++) z3[o] += w2s[o*H1 + o2] * s;
    }
    float* hrow = &g_h[(size_t)(b * L1 + t) * C1];
#pragma unroll
    for (int c = 0; c < CIN; c++) hrow[c] = xr[KS-1][c];
    hrow[CIN] = (float)t * (1.0f / (float)(L1 - 1));
#pragma unroll
    for (int o = 0; o < H2; o++) hrow[CIN + 1 + o] = z3[o];
}

// ============================================================
// Sig1 passes
// ============================================================
__global__ __launch_bounds__(512) void k_sig1_sum() {
    __shared__ float hs[CH1 + 1][C1];
    int b = blockIdx.y, nc = blockIdx.x, tid = threadIdx.x;
    int c0 = nc * CH1;
    for (int idx = tid; idx < (CH1 + 1) * C1; idx += 512) {
        int r = idx / C1, c = idx - r * C1;
        int row = c0 - 1 + r;
        hs[r][c] = (row >= 0 && row < L1) ? g_h[(size_t)(b * L1 + row) * C1 + c] : 0.f;
    }
    __syncthreads();
    if (tid >= C1 * C1) return;
    int i = tid / C1, j = tid - i * C1;
    float acc = 0.f;
    int tend = min(c0 + CH1, L1);
    for (int t = c0; t < tend; t++) {
        int r = t - c0 + 1;
        float hpi = hs[r-1][i], hpj = hs[r-1][j];
        float dxi = hs[r][i] - hpi, dxj = hs[r][j] - hpj;
        acc += hpi * dxj + 0.5f * dxi * dxj;
    }
    g_csum[(b * NC1 + nc) * SC1P + tid] = acc;
}

__global__ void k_sig1_prefix() {
    int b = blockIdx.x, tid = threadIdx.x;
    if (tid >= C1 * C1) return;
    float run = 0.f;
    for (int nc = 0; nc < NC1; nc++) {
        int idx = (b * NC1 + nc) * SC1P + tid;
        float v = g_csum[idx];
        g_csum[idx] = run;
        run += v;
    }
}

__global__ __launch_bounds__(512) void k_sig1_write() {
    __shared__ float hs[CH1 + 1][C1];
    int b = blockIdx.y, nc = blockIdx.x, tid = threadIdx.x;
    int c0 = nc * CH1;
    for (int idx = tid; idx < (CH1 + 1) * C1; idx += 512) {
        int r = idx / C1, c = idx - r * C1;
        int row = c0 - 1 + r;
        hs[r][c] = (row >= 0 && row < L1) ? g_h[(size_t)(b * L1 + row) * C1 + c] : 0.f;
    }
    __syncthreads();
    int tend = min(c0 + CH1, L1);
    if (tid < C1 * C1) {
        int i = tid / C1, j = tid - i * C1;
        float acc = g_csum[(b * NC1 + nc) * SC1P + tid];
        for (int t = c0; t < tend; t++) {
            int r = t - c0 + 1;
            float hpi = hs[r-1][i], hpj = hs[r-1][j];
            float dxi = hs[r][i] - hpi, dxj = hs[r][j] - hpj;
            acc += hpi * dxj + 0.5f * dxi * dxj;
            g_s1[((size_t)(b * L1 + t)) * SC1P + C1 + tid] = acc;
        }
    } else {
        int c = tid - C1 * C1;
        int ch = (c < C1) ? c : (C1 * C1 + c);
        for (int t = c0; t < tend; t++) {
            int r = t - c0 + 1;
            float v = (c < C1) ? hs[r][c] : 0.f;
            g_s1[((size_t)(b * L1 + t)) * SC1P + ch] = v;
        }
    }
}

// ============================================================
// Conv stack 2: 128x64 GEMM (K=2048), FFMA2, KC=32, dup-B
// ============================================================
__global__ __launch_bounds__(256, 4) void k_conv2(
    const float* __restrict__ b0,
    const float* __restrict__ w1, const float* __restrict__ b1,
    const float* __restrict__ w2, const float* __restrict__ b2)
{
    extern __shared__ float dsm[];
    float* As = dsm;               // [KC][SAS]  c-major, m contiguous
    float* Bs = dsm + KC * SAS;    // [KC][128]  duplicated pairs
    float* Z  = dsm;               // [128][SZ]
    float* Wm = dsm + 128 * SZ;    // [64][SW]
    __shared__ float b0s[64], b1s[64], b2s[16];

    int tid = threadIdx.x;
    int b = blockIdx.y, t0 = blockIdx.x * TM;
    if (tid < 64) { b0s[tid] = b0[tid]; b1s[tid] = b1[tid]; }
    if (tid < 16) b2s[tid] = b2[tid];

    int tx = tid & 15, ty = tid >> 4;
    int m0 = ty * 8, n0 = tx * 4;

    unsigned long long acc2[4][4];
#pragma unroll
    for (int p = 0; p < 4; p++)
#pragma unroll
        for (int j = 0; j < 4; j++) acc2[p][j] = 0ULL;

    const float* pAbase = g_s1 + (size_t)b * L1 * SC1P;
    for (int kb = 0; kb < 64; kb++) {
        int kk = kb >> 4;
        int cb = (kb & 15) << 5;          // 32-channel chunk
        // A tile: 128 rows x 32 ch -> As[c][m]
#pragma unroll
        for (int q = 0; q < 4; q++) {
            int idx = tid + q * 256;      // 0..1023
            int m = idx >> 3, c4 = idx & 7;
            int row = t0 + kk + m;
            float4 v = make_float4(0.f, 0.f, 0.f, 0.f);
            if (row < L1)
                v = *(const float4*)&pAbase[(size_t)row * SC1P + cb + c4 * 4];
            As[(c4*4+0)*SAS + m] = v.x;
            As[(c4*4+1)*SAS + m] = v.y;
            As[(c4*4+2)*SAS + m] = v.z;
            As[(c4*4+3)*SAS + m] = v.w;
        }
        const float4* pB = (const float4*)(g_wdup + (kk * SC1P + cb) * 128);
#pragma unroll
        for (int q = 0; q < 4; q++)
            ((float4*)Bs)[tid + q * 256] = pB[tid + q * 256];
        __syncthreads();
#pragma unroll
        for (int k = 0; k < KC; k++) {
            const unsigned long long* pw = (const unsigned long long*)&Bs[k * 128 + 2 * n0];
            unsigned long long wp0 = pw[0], wp1 = pw[1], wp2 = pw[2], wp3 = pw[3];
            const unsigned long long* pa = (const unsigned long long*)&As[k * SAS + m0];
            unsigned long long a0 = pa[0], a1 = pa[1], a2v = pa[2], a3 = pa[3];
            acc2[0][0] = ffma2(a0, wp0, acc2[0][0]);
            acc2[0][1] = ffma2(a0, wp1, acc2[0][1]);
            acc2[0][2] = ffma2(a0, wp2, acc2[0][2]);
            acc2[0][3] = ffma2(a0, wp3, acc2[0][3]);
            acc2[1][0] = ffma2(a1, wp0, acc2[1][0]);
            acc2[1][1] = ffma2(a1, wp1, acc2[1][1]);
            acc2[1][2] = ffma2(a1, wp2, acc2[1][2]);
            acc2[1][3] = ffma2(a1, wp3, acc2[1][3]);
            acc2[2][0] = ffma2(a2v, wp0, acc2[2][0]);
            acc2[2][1] = ffma2(a2v, wp1, acc2[2][1]);
            acc2[2][2] = ffma2(a2v, wp2, acc2[2][2]);
            acc2[2][3] = ffma2(a2v, wp3, acc2[2][3]);
            acc2[3][0] = ffma2(a3, wp0, acc2[3][0]);
            acc2[3][1] = ffma2(a3, wp1, acc2[3][1]);
            acc2[3][2] = ffma2(a3, wp2, acc2[3][2]);
            acc2[3][3] = ffma2(a3, wp3, acc2[3][3]);
        }
        __syncthreads();
    }

    // ---- epilogue ----
#pragma unroll
    for (int p = 0; p < 4; p++)
#pragma unroll
        for (int j = 0; j < 4; j++) {
            float lo, hi;
            unpack2(acc2[p][j], lo, hi);
            Z[(m0 + 2*p    ) * SZ + n0 + j] = fmaxf(lo + b0s[n0 + j], 0.f);
            Z[(m0 + 2*p + 1) * SZ + n0 + j] = fmaxf(hi + b0s[n0 + j], 0.f);
        }
#pragma unroll
    for (int q = 0; q < 16; q++) {
        int idx = tid + q * 256;
        Wm[(idx & 63) * SW + (idx >> 6)] = w1[idx];
    }
    __syncthreads();

    float a2[8][4];
#pragma unroll
    for (int i = 0; i < 8; i++)
#pragma unroll
        for (int j = 0; j < 4; j++) a2[i][j] = b1s[n0 + j];
#pragma unroll 4
    for (int c = 0; c < 64; c++) {
        float4 wv = *(const float4*)&Wm[c * SW + n0];
#pragma unroll
        for (int i = 0; i < 8; i++) {
            float zi = Z[(m0 + i) * SZ + c];
            a2[i][0] += zi * wv.x; a2[i][1] += zi * wv.y;
            a2[i][2] += zi * wv.z; a2[i][3] += zi * wv.w;
        }
    }
    __syncthreads();
#pragma unroll
    for (int i = 0; i < 8; i++)
#pragma unroll
        for (int j = 0; j < 4; j++)
            Z[(m0 + i) * SZ + n0 + j] = fmaxf(a2[i][j], 0.f);
#pragma unroll
    for (int q = 0; q < 4; q++) {
        int idx = tid + q * 256;
        Wm[(idx >> 6) * SW + (idx & 63)] = w2[idx];
    }
    __syncthreads();
    int o3 = tid & 15;
    int mb = tid >> 4;
#pragma unroll
    for (int g2 = 0; g2 < 8; g2++) {
        int m = mb + g2 * 16;
        float s = b2s[o3];
#pragma unroll 16
        for (int c = 0; c < 64; c++) s += Wm[o3 * SW + c] * Z[m * SZ + c];
        int t = t0 + m;
        if (t < L2) g_h2[(size_t)(b * L2 + t) * H2 + o3] = s;
    }
}

// ============================================================
// become_constant + sig2 + linear
// ============================================================
__global__ __launch_bounds__(256) void k_sig2(
    const int* __restrict__ lengths,
    const float* __restrict__ lw, const float* __restrict__ lb,
    float* __restrict__ out)
{
    __shared__ float hs[129][16];
    __shared__ float s2s[SIGC2];
    int b = blockIdx.x, tid = threadIdx.x;
    int adj = lengths[b] - 2 * KS + 2;
    if (adj < 1) adj = 1;
    if (adj > L2) adj = L2;
    int i = tid >> 4, j = tid & 15;
    float acc = 0.f;
    for (int c0 = 0; c0 < adj; c0 += 128) {
        for (int idx = tid; idx < 129 * 16; idx += 256) {
            int r = idx >> 4, c = idx & 15;
            int row = c0 - 1 + r;
            hs[r][c] = (row >= 0 && row < L2) ? g_h2[(size_t)(b * L2 + row) * H2 + c] : 0.f;
        }
        __syncthreads();
        int tend = min(c0 + 128, adj);
        for (int t = c0; t < tend; t++) {
            int r = t - c0 + 1;
            float hpi = hs[r-1][i], hpj = hs[r-1][j];
            float dxi = hs[r][i] - hpi, dxj = hs[r][j] - hpj;
            acc += hpi * dxj + 0.5f * dxi * dxj;
        }
        __syncthreads();
    }
    s2s[16 + tid] = acc;
    if (tid < 16) s2s[tid] = g_h2[(size_t)(b * L2 + adj - 1) * H2 + tid];
    __syncthreads();
    if (tid < OUTC) {
        float v = lb[tid];
        for (int c = 0; c < SIGC2; c++) v += lw[tid * SIGC2 + c] * s2s[c];
        out[b * OUTC + tid] = v;
    }
}

// ============================================================
extern "C" void kernel_launch(void* const* d_in, const int* in_sizes, int n_in,
                              void* d_out, int out_size) {
    const float* x      = (const float*)d_in[0];
    const int*   lens   = (const int*)  d_in[1];
    const float* a1_w0  = (const float*)d_in[2];
    const float* a1_b0  = (const float*)d_in[3];
    const float* a1_w1  = (const float*)d_in[4];
    const float* a1_b1  = (const float*)d_in[5];
    const float* a1_w2  = (const float*)d_in[6];
    const float* a1_b2  = (const float*)d_in[7];
    const float* a2_w0  = (const float*)d_in[8];
    const float* a2_b0  = (const float*)d_in[9];
    const float* a2_w1  = (const float*)d_in[10];
    const float* a2_b1  = (const float*)d_in[11];
    const float* a2_w2  = (const float*)d_in[12];
    const float* a2_b2  = (const float*)d_in[13];
    const float* lin_w  = (const float*)d_in[14];
    const float* lin_b  = (const float*)d_in[15];
    float* out = (float*)d_out;

    static bool attr_set = false;
    if (!attr_set) {
        cudaFuncSetAttribute(k_conv2, cudaFuncAttributeMaxDynamicSharedMemorySize, DSMB);
        attr_set = true;
    }

    k_repack<<<1024, 256>>>(a2_w0);
    k_aug1<<<dim3(8, B_), 128>>>(x, a1_w0, a1_b0, a1_w1, a1_b1, a1_w2, a1_b2);
    k_sig1_sum<<<dim3(NC1, B_), 512>>>();
    k_sig1_prefix<<<B_, 512>>>();
    k_sig1_write<<<dim3(NC1, B_), 512>>>();
    k_conv2<<<dim3(8, B_), 256, DSMB>>>(a2_b0, a2_w1, a2_b1, a2_w2, a2_b2);
    k_sig2<<<B_, 256>>>(lens, lin_w, lin_b, out);
}

// round 5
// speedup vs baseline: 1.4966x; 1.4966x over previous
#include <cuda_runtime.h>
#include <cstdint>

#define B_    64
#define S_    1024
#define CIN   5
#define KS    4
#define H1    64
#define H2    16
#define OUTC  32
#define L1    1021
#define C1    22
#define SIGC1 506
#define SC1P  512
#define L2    1018
#define SIGC2 272
#define NC1   16
#define CH1   64

// conv2 tiling (R3 geometry)
#define TM    128
#define SAS   130
#define SZ    66
#define SW    68
#define GEMMF (64*SAS + 64*64)           // 8320 + 4096 = 12416
#define EPIF  (128*SZ + 64*SW)           // 8448 + 4352 = 12800
#define DSMF  (GEMMF > EPIF ? GEMMF : EPIF)
#define DSMB  (DSMF * 4)

// ---- scratch ----
__device__ float g_h[B_ * L1 * C1];
__device__ float g_s1[(size_t)B_ * L1 * SC1P];
__device__ float g_wpad[KS * SC1P * H1];
__device__ float g_csum[B_ * NC1 * SC1P];
__device__ float g_h2[B_ * L2 * H2];

__device__ __forceinline__ unsigned long long ffma2(
    unsigned long long a, unsigned long long b, unsigned long long c) {
    unsigned long long d;
    asm("fma.rn.f32x2 %0, %1, %2, %3;" : "=l"(d) : "l"(a), "l"(b), "l"(c));
    return d;
}
__device__ __forceinline__ unsigned long long pack2(float v) {
    unsigned long long d;
    unsigned int r = __float_as_uint(v);
    asm("mov.b64 %0, {%1, %1};" : "=l"(d) : "r"(r));
    return d;
}
__device__ __forceinline__ void unpack2(unsigned long long p, float& lo, float& hi) {
    unsigned int a, b;
    asm("mov.b64 {%0, %1}, %2;" : "=r"(a), "=r"(b) : "l"(p));
    lo = __uint_as_float(a); hi = __uint_as_float(b);
}

// ============================================================
// Repack a2_w0 (O,C,K) -> wpad[k][c_pad][o]
// ============================================================
__global__ void k_repack(const float* __restrict__ w0) {
    int idx = blockIdx.x * blockDim.x + threadIdx.x;
    int o  = idx & 63;
    int c  = (idx >> 6) & (SC1P - 1);
    int kk = idx >> 15;
    float v = 0.f;
    if (c < SIGC1) v = w0[(o * SIGC1 + c) * KS + kk];
    g_wpad[idx] = v;
}

// ============================================================
// Augment 1
// ============================================================
__global__ __launch_bounds__(128) void k_aug1(
    const float* __restrict__ x,
    const float* __restrict__ w0, const float* __restrict__ b0,
    const float* __restrict__ w1, const float* __restrict__ b1,
    const float* __restrict__ w2, const float* __restrict__ b2)
{
    __shared__ float w0s[H1*CIN*KS], w1s[H1*H1], w2s[H2*H1];
    __shared__ float b0s[H1], b1s[H1], b2s[H2];
    int tid = threadIdx.x;
    for (int i = tid; i < H1*CIN*KS; i += 128) w0s[i] = w0[i];
    for (int i = tid; i < H1*H1;     i += 128) w1s[i] = w1[i];
    for (int i = tid; i < H2*H1;     i += 128) w2s[i] = w2[i];
    if (tid < H1) { b0s[tid] = b0[tid]; b1s[tid] = b1[tid]; }
    if (tid < H2) b2s[tid] = b2[tid];
    __syncthreads();

    int b = blockIdx.y;
    int t = blockIdx.x * 128 + tid;
    if (t >= L1) return;

    float xr[KS][CIN];
#pragma unroll
    for (int k = 0; k < KS; k++)
#pragma unroll
        for (int c = 0; c < CIN; c++)
            xr[k][c] = x[((size_t)(b * S_) + t + k) * CIN + c];

    float z1[H1];
#pragma unroll
    for (int o = 0; o < H1; o++) {
        float s = b0s[o];
#pragma unroll
        for (int c = 0; c < CIN; c++)
#pragma unroll
            for (int k = 0; k < KS; k++)
                s += w0s[(o*CIN + c)*KS + k] * xr[k][c];
        z1[o] = fmaxf(s, 0.f);
    }
    float z3[H2];
#pragma unroll
    for (int o = 0; o < H2; o++) z3[o] = b2s[o];
    for (int o2 = 0; o2 < H1; o2++) {
        float s = b1s[o2];
#pragma unroll
        for (int c = 0; c < H1; c++) s += w1s[o2*H1 + c] * z1[c];
        s = fmaxf(s, 0.f);
#pragma unroll
        for (int o = 0; o < H2; o++) z3[o] += w2s[o*H1 + o2] * s;
    }
    float* hrow = &g_h[(size_t)(b * L1 + t) * C1];
#pragma unroll
    for (int c = 0; c < CIN; c++) hrow[c] = xr[KS-1][c];
    hrow[CIN] = (float)t * (1.0f / (float)(L1 - 1));
#pragma unroll
    for (int o = 0; o < H2; o++) hrow[CIN + 1 + o] = z3[o];
}

// ============================================================
// Sig1 passes
// ============================================================
__global__ __launch_bounds__(512) void k_sig1_sum() {
    __shared__ float hs[CH1 + 1][C1];
    int b = blockIdx.y, nc = blockIdx.x, tid = threadIdx.x;
    int c0 = nc * CH1;
    for (int idx = tid; idx < (CH1 + 1) * C1; idx += 512) {
        int r = idx / C1, c = idx - r * C1;
        int row = c0 - 1 + r;
        hs[r][c] = (row >= 0 && row < L1) ? g_h[(size_t)(b * L1 + row) * C1 + c] : 0.f;
    }
    __syncthreads();
    if (tid >= C1 * C1) return;
    int i = tid / C1, j = tid - i * C1;
    float acc = 0.f;
    int tend = min(c0 + CH1, L1);
    for (int t = c0; t < tend; t++) {
        int r = t - c0 + 1;
        float hpi = hs[r-1][i], hpj = hs[r-1][j];
        float dxi = hs[r][i] - hpi, dxj = hs[r][j] - hpj;
        acc += hpi * dxj + 0.5f * dxi * dxj;
    }
    g_csum[(b * NC1 + nc) * SC1P + tid] = acc;
}

__global__ void k_sig1_prefix() {
    int b = blockIdx.x, tid = threadIdx.x;
    if (tid >= C1 * C1) return;
    float run = 0.f;
    for (int nc = 0; nc < NC1; nc++) {
        int idx = (b * NC1 + nc) * SC1P + tid;
        float v = g_csum[idx];
        g_csum[idx] = run;
        run += v;
    }
}

__global__ __launch_bounds__(512) void k_sig1_write() {
    __shared__ float hs[CH1 + 1][C1];
    int b = blockIdx.y, nc = blockIdx.x, tid = threadIdx.x;
    int c0 = nc * CH1;
    for (int idx = tid; idx < (CH1 + 1) * C1; idx += 512) {
        int r = idx / C1, c = idx - r * C1;
        int row = c0 - 1 + r;
        hs[r][c] = (row >= 0 && row < L1) ? g_h[(size_t)(b * L1 + row) * C1 + c] : 0.f;
    }
    __syncthreads();
    int tend = min(c0 + CH1, L1);
    if (tid < C1 * C1) {
        int i = tid / C1, j = tid - i * C1;
        float acc = g_csum[(b * NC1 + nc) * SC1P + tid];
        for (int t = c0; t < tend; t++) {
            int r = t - c0 + 1;
            float hpi = hs[r-1][i], hpj = hs[r-1][j];
            float dxi = hs[r][i] - hpi, dxj = hs[r][j] - hpj;
            acc += hpi * dxj + 0.5f * dxi * dxj;
            g_s1[((size_t)(b * L1 + t)) * SC1P + C1 + tid] = acc;
        }
    } else {
        int c = tid - C1 * C1;
        int ch = (c < C1) ? c : (C1 * C1 + c);
        for (int t = c0; t < tend; t++) {
            int r = t - c0 + 1;
            float v = (c < C1) ? hs[r][c] : 0.f;
            g_s1[((size_t)(b * L1 + t)) * SC1P + ch] = v;
        }
    }
}

// ============================================================
// Conv stack 2: 128x64 GEMM (K=2048), FFMA2, KC=64,
// register-prefetch software pipeline + fused epilogue
// ============================================================
__global__ __launch_bounds__(256) void k_conv2(
    const float* __restrict__ b0,
    const float* __restrict__ w1, const float* __restrict__ b1,
    const float* __restrict__ w2, const float* __restrict__ b2)
{
    extern __shared__ float dsm[];
    float* As = dsm;               // [64][SAS]  c-major, m contiguous
    float* Bs = dsm + 64 * SAS;    // [64][64]
    float* Z  = dsm;               // [128][SZ]
    float* Wm = dsm + 128 * SZ;    // [64][SW]
    __shared__ float b0s[64], b1s[64], b2s[16];

    int tid = threadIdx.x;
    int b = blockIdx.y, t0 = blockIdx.x * TM;
    if (tid < 64) { b0s[tid] = b0[tid]; b1s[tid] = b1[tid]; }
    if (tid < 16) b2s[tid] = b2[tid];

    int tx = tid & 15, ty = tid >> 4;
    int m0 = ty * 8, n0 = tx * 4;

    unsigned long long acc2[4][4];
#pragma unroll
    for (int p = 0; p < 4; p++)
#pragma unroll
        for (int j = 0; j < 4; j++) acc2[p][j] = 0ULL;

    const float* pAbase = g_s1 + (size_t)b * L1 * SC1P;

    // prefetch registers
    float4 pfA[8];
    float4 pfB[4];

    // A fill mapping: idx = tid + q*256; m = idx>>4, c4 = idx&15
    int am = tid >> 4;             // row within 32-row group, repeated per q
    int ac4 = tid & 15;

#define PREFETCH(kb_) do {                                                  \
        int kk_ = (kb_) >> 3;                                               \
        int cb_ = ((kb_) & 7) << 6;                                         \
        _Pragma("unroll")                                                   \
        for (int q = 0; q < 8; q++) {                                       \
            int m_ = am + ((q & 3) << 5) + ((q >> 2) << 4) - ((q>>2)<<4);   \
            (void)m_;                                                       \
            int idx_ = tid + q * 256;                                       \
            int mm_ = idx_ >> 4;                                            \
            int row_ = t0 + kk_ + mm_;                                      \
            pfA[q] = make_float4(0.f, 0.f, 0.f, 0.f);                       \
            if (row_ < L1)                                                  \
                pfA[q] = *(const float4*)&pAbase[(size_t)row_ * SC1P + cb_ + ac4 * 4]; \
        }                                                                   \
        const float4* pB_ = (const float4*)(g_wpad + (kk_ * SC1P + cb_) * 64); \
        _Pragma("unroll")                                                   \
        for (int q = 0; q < 4; q++) pfB[q] = pB_[tid + q * 256];            \
    } while (0)

    PREFETCH(0);

    for (int kb = 0; kb < 32; kb++) {
        // store prefetched chunk to smem
#pragma unroll
        for (int q = 0; q < 8; q++) {
            int idx = tid + q * 256;
            int m = idx >> 4;
            As[(ac4*4+0)*SAS + m] = pfA[q].x;
            As[(ac4*4+1)*SAS + m] = pfA[q].y;
            As[(ac4*4+2)*SAS + m] = pfA[q].z;
            As[(ac4*4+3)*SAS + m] = pfA[q].w;
        }
#pragma unroll
        for (int q = 0; q < 4; q++)
            ((float4*)Bs)[tid + q * 256] = pfB[q];
        __syncthreads();

        if (kb + 1 < 32) PREFETCH(kb + 1);

#pragma unroll
        for (int k = 0; k < 64; k++) {
            float4 wv = *(const float4*)&Bs[k * 64 + n0];
            unsigned long long wp0 = pack2(wv.x), wp1 = pack2(wv.y);
            unsigned long long wp2 = pack2(wv.z), wp3 = pack2(wv.w);
            const unsigned long long* pa = (const unsigned long long*)&As[k * SAS + m0];
            unsigned long long a0 = pa[0], a1 = pa[1], a2v = pa[2], a3 = pa[3];
            acc2[0][0] = ffma2(a0, wp0, acc2[0][0]);
            acc2[0][1] = ffma2(a0, wp1, acc2[0][1]);
            acc2[0][2] = ffma2(a0, wp2, acc2[0][2]);
            acc2[0][3] = ffma2(a0, wp3, acc2[0][3]);
            acc2[1][0] = ffma2(a1, wp0, acc2[1][0]);
            acc2[1][1] = ffma2(a1, wp1, acc2[1][1]);
            acc2[1][2] = ffma2(a1, wp2, acc2[1][2]);
            acc2[1][3] = ffma2(a1, wp3, acc2[1][3]);
            acc2[2][0] = ffma2(a2v, wp0, acc2[2][0]);
            acc2[2][1] = ffma2(a2v, wp1, acc2[2][1]);
            acc2[2][2] = ffma2(a2v, wp2, acc2[2][2]);
            acc2[2][3] = ffma2(a2v, wp3, acc2[2][3]);
            acc2[3][0] = ffma2(a3, wp0, acc2[3][0]);
            acc2[3][1] = ffma2(a3, wp1, acc2[3][1]);
            acc2[3][2] = ffma2(a3, wp2, acc2[3][2]);
            acc2[3][3] = ffma2(a3, wp3, acc2[3][3]);
        }
        __syncthreads();
    }

    // ---- epilogue ----
#pragma unroll
    for (int p = 0; p < 4; p++)
#pragma unroll
        for (int j = 0; j < 4; j++) {
            float lo, hi;
            unpack2(acc2[p][j], lo, hi);
            Z[(m0 + 2*p    ) * SZ + n0 + j] = fmaxf(lo + b0s[n0 + j], 0.f);
            Z[(m0 + 2*p + 1) * SZ + n0 + j] = fmaxf(hi + b0s[n0 + j], 0.f);
        }
#pragma unroll
    for (int q = 0; q < 16; q++) {
        int idx = tid + q * 256;
        Wm[(idx & 63) * SW + (idx >> 6)] = w1[idx];
    }
    __syncthreads();

    float a2[8][4];
#pragma unroll
    for (int i = 0; i < 8; i++)
#pragma unroll
        for (int j = 0; j < 4; j++) a2[i][j] = b1s[n0 + j];
#pragma unroll 4
    for (int c = 0; c < 64; c++) {
        float4 wv = *(const float4*)&Wm[c * SW + n0];
#pragma unroll
        for (int i = 0; i < 8; i++) {
            float zi = Z[(m0 + i) * SZ + c];
            a2[i][0] += zi * wv.x; a2[i][1] += zi * wv.y;
            a2[i][2] += zi * wv.z; a2[i][3] += zi * wv.w;
        }
    }
    __syncthreads();
#pragma unroll
    for (int i = 0; i < 8; i++)
#pragma unroll
        for (int j = 0; j < 4; j++)
            Z[(m0 + i) * SZ + n0 + j] = fmaxf(a2[i][j], 0.f);
#pragma unroll
    for (int q = 0; q < 4; q++) {
        int idx = tid + q * 256;
        Wm[(idx >> 6) * SW + (idx & 63)] = w2[idx];
    }
    __syncthreads();
    int o3 = tid & 15;
    int mb = tid >> 4;
#pragma unroll
    for (int g2 = 0; g2 < 8; g2++) {
        int m = mb + g2 * 16;
        float s = b2s[o3];
#pragma unroll 16
        for (int c = 0; c < 64; c++) s += Wm[o3 * SW + c] * Z[m * SZ + c];
        int t = t0 + m;
        if (t < L2) g_h2[(size_t)(b * L2 + t) * H2 + o3] = s;
    }
}

// ============================================================
// become_constant + sig2 + linear
// ============================================================
__global__ __launch_bounds__(256) void k_sig2(
    const int* __restrict__ lengths,
    const float* __restrict__ lw, const float* __restrict__ lb,
    float* __restrict__ out)
{
    __shared__ float hs[129][16];
    __shared__ float s2s[SIGC2];
    int b = blockIdx.x, tid = threadIdx.x;
    int adj = lengths[b] - 2 * KS + 2;
    if (adj < 1) adj = 1;
    if (adj > L2) adj = L2;
    int i = tid >> 4, j = tid & 15;
    float acc = 0.f;
    for (int c0 = 0; c0 < adj; c0 += 128) {
        for (int idx = tid; idx < 129 * 16; idx += 256) {
            int r = idx >> 4, c = idx & 15;
            int row = c0 - 1 + r;
            hs[r][c] = (row >= 0 && row < L2) ? g_h2[(size_t)(b * L2 + row) * H2 + c] : 0.f;
        }
        __syncthreads();
        int tend = min(c0 + 128, adj);
        for (int t = c0; t < tend; t++) {
            int r = t - c0 + 1;
            float hpi = hs[r-1][i], hpj = hs[r-1][j];
            float dxi = hs[r][i] - hpi, dxj = hs[r][j] - hpj;
            acc += hpi * dxj + 0.5f * dxi * dxj;
        }
        __syncthreads();
    }
    s2s[16 + tid] = acc;
    if (tid < 16) s2s[tid] = g_h2[(size_t)(b * L2 + adj - 1) * H2 + tid];
    __syncthreads();
    if (tid < OUTC) {
        float v = lb[tid];
        for (int c = 0; c < SIGC2; c++) v += lw[tid * SIGC2 + c] * s2s[c];
        out[b * OUTC + tid] = v;
    }
}

// ============================================================
extern "C" void kernel_launch(void* const* d_in, const int* in_sizes, int n_in,
                              void* d_out, int out_size) {
    const float* x      = (const float*)d_in[0];
    const int*   lens   = (const int*)  d_in[1];
    const float* a1_w0  = (const float*)d_in[2];
    const float* a1_b0  = (const float*)d_in[3];
    const float* a1_w1  = (const float*)d_in[4];
    const float* a1_b1  = (const float*)d_in[5];
    const float* a1_w2  = (const float*)d_in[6];
    const float* a1_b2  = (const float*)d_in[7];
    const float* a2_w0  = (const float*)d_in[8];
    const float* a2_b0  = (const float*)d_in[9];
    const float* a2_w1  = (const float*)d_in[10];
    const float* a2_b1  = (const float*)d_in[11];
    const float* a2_w2  = (const float*)d_in[12];
    const float* a2_b2  = (const float*)d_in[13];
    const float* lin_w  = (const float*)d_in[14];
    const float* lin_b  = (const float*)d_in[15];
    float* out = (float*)d_out;

    static bool attr_set = false;
    if (!attr_set) {
        cudaFuncSetAttribute(k_conv2, cudaFuncAttributeMaxDynamicSharedMemorySize, DSMB);
        attr_set = true;
    }

    k_repack<<<512, 256>>>(a2_w0);
    k_aug1<<<dim3(8, B_), 128>>>(x, a1_w0, a1_b0, a1_w1, a1_b1, a1_w2, a1_b2);
    k_sig1_sum<<<dim3(NC1, B_), 512>>>();
    k_sig1_prefix<<<B_, 512>>>();
    k_sig1_write<<<dim3(NC1, B_), 512>>>();
    k_conv2<<<dim3(8, B_), 256, DSMB>>>(a2_b0, a2_w1, a2_b1, a2_w2, a2_b2);
    k_sig2<<<B_, 256>>>(lens, lin_w, lin_b, out);
}